// round 16
// baseline (speedup 1.0000x reference)
#include <cuda_runtime.h>
#include <cuda_fp16.h>
#include <cstdint>

#define NN 100000
#define EE 200000
#define BBATCH 2048
#define HH 256
#define HB2 512
#define LLAYERS 4

// ------------------------- scratch (device globals; no allocs) ---------------
__device__ float g_h[(size_t)NN * HH];
__device__ float g_hn[(size_t)NN * HH];             // fp32 hn (final layer only)
__device__ uint32_t g_hnh[(size_t)NN * (HH / 2)];   // half2-packed hn (layers)
__device__ uint32_t g_tmph[(size_t)NN * (HH / 2)];  // half2-packed A for GEMM1
__device__ uint32_t g_midh[(size_t)NN * (HB2 / 2)]; // half2-packed A for GEMM2
__device__ uint32_t g_w1h[3 * (HH / 2) * HB2];      // [kp][n] packed W1
__device__ uint32_t g_w2h[3 * (HB2 / 2) * HH];      // [kp][n] packed W2
__device__ float g_vn[BBATCH * HH];
__device__ float g_vnsum[BBATCH * HH];
__device__ float g_inv[BBATCH];
__device__ int g_deg[NN];
__device__ int g_indptr[NN + 1];
__device__ int g_cursor[NN];
__device__ int g_csr[EE];
__device__ int g_cnt[BBATCH];
__device__ int g_bsums[128];
__device__ int g_boffs[128];

// ------------------------- small helpers -------------------------------------
__device__ __forceinline__ uint32_t pack_h2(float a, float b) {
    __half2 h = __floats2half2_rn(a, b);
    return *reinterpret_cast<uint32_t*>(&h);
}
__device__ __forceinline__ float2 unpack_h2(uint32_t u) {
    return __half22float2(*reinterpret_cast<__half2*>(&u));
}

__device__ __forceinline__ void mma_f16(float* c, const uint32_t* a, const uint32_t* b) {
    asm volatile(
        "mma.sync.aligned.m16n8k16.row.col.f32.f16.f16.f32 "
        "{%0,%1,%2,%3},{%4,%5,%6,%7},{%8,%9},{%0,%1,%2,%3};"
        : "+f"(c[0]), "+f"(c[1]), "+f"(c[2]), "+f"(c[3])
        : "r"(a[0]), "r"(a[1]), "r"(a[2]), "r"(a[3]), "r"(b[0]), "r"(b[1]));
}

__device__ __forceinline__ void cp16(uint32_t dst, const void* src, int bytes) {
    asm volatile("cp.async.cg.shared.global [%0], [%1], 16, %2;\n" ::"r"(dst), "l"(src),
                 "r"(bytes));
}
__device__ __forceinline__ void cp_commit() { asm volatile("cp.async.commit_group;\n"); }
template <int W>
__device__ __forceinline__ void cp_wait() {
    asm volatile("cp.async.wait_group %0;\n" ::"n"(W));
}

// ------------------------- setup kernels -------------------------------------
__global__ void zero_setup() {
    int i = blockIdx.x * blockDim.x + threadIdx.x;
    if (i < NN) { g_deg[i] = 0; g_cursor[i] = 0; }
    if (i < BBATCH) g_cnt[i] = 0;
}

__global__ void zero_f(float* p, int n) {
    int i = blockIdx.x * blockDim.x + threadIdx.x;
    if (i < n) p[i] = 0.0f;
}

__global__ void count_deg(const int* __restrict__ dst) {
    int e = blockIdx.x * blockDim.x + threadIdx.x;
    if (e < EE) atomicAdd(&g_deg[dst[e]], 1);
}

__global__ void count_batch(const int* __restrict__ batch) {
    int n = blockIdx.x * blockDim.x + threadIdx.x;
    if (n < NN) atomicAdd(&g_cnt[batch[n]], 1);
}

__global__ void scan_block() {
    __shared__ int s[1024];
    int i = blockIdx.x * 1024 + threadIdx.x;
    int v = (i < NN) ? g_deg[i] : 0;
    s[threadIdx.x] = v;
    __syncthreads();
#pragma unroll
    for (int off = 1; off < 1024; off <<= 1) {
        int t = (threadIdx.x >= off) ? s[threadIdx.x - off] : 0;
        __syncthreads();
        s[threadIdx.x] += t;
        __syncthreads();
    }
    if (i < NN) g_indptr[i + 1] = s[threadIdx.x];
    if (threadIdx.x == 1023) g_bsums[blockIdx.x] = s[1023];
    if (i == 0) g_indptr[0] = 0;
}

__global__ void scan_sums(int nb) {
    __shared__ int s[128];
    int t = threadIdx.x;
    int v = (t < nb) ? g_bsums[t] : 0;
    s[t] = v;
    __syncthreads();
#pragma unroll
    for (int off = 1; off < 128; off <<= 1) {
        int u = (t >= off) ? s[t - off] : 0;
        __syncthreads();
        s[t] += u;
        __syncthreads();
    }
    if (t < nb) g_boffs[t] = s[t] - v;
}

__global__ void add_offs() {
    int i = blockIdx.x * blockDim.x + threadIdx.x;
    if (i < NN) g_indptr[i + 1] += g_boffs[i >> 10];
}

__global__ void csr_fill(const int* __restrict__ dst) {
    int e = blockIdx.x * blockDim.x + threadIdx.x;
    if (e < EE) {
        int d = dst[e];
        int p = atomicAdd(&g_cursor[d], 1);
        g_csr[g_indptr[d] + p] = e;
    }
}

__global__ void calc_inv() {
    int b = blockIdx.x * blockDim.x + threadIdx.x;
    if (b < BBATCH) g_inv[b] = 1.0f / fmaxf((float)g_cnt[b], 1.0f);
}

__global__ void vn_init(float* __restrict__ vn, const float* __restrict__ emb) {
    int i = blockIdx.x * blockDim.x + threadIdx.x;
    if (i < BBATCH * HH) vn[i] = emb[i & (HH - 1)];
}

// pack W[K][N] fp32 -> [K/2][N] u32 (half2 along k)
__global__ void packWh(const float* __restrict__ W, uint32_t* __restrict__ o, int K, int N) {
    int i = blockIdx.x * blockDim.x + threadIdx.x;
    int tot = (K / 2) * N;
    if (i >= tot) return;
    int kp = i / N, n = i % N;
    o[i] = pack_h2(W[(2 * kp) * N + n], W[(2 * kp + 1) * N + n]);
}

// ------------------------- node encoder -------------------------------------
__global__ void node_enc(const float* __restrict__ x, const float* __restrict__ W,
                         const float* __restrict__ b, float* __restrict__ h) {
    __shared__ float xs[9];
    int n = blockIdx.x;
    if (threadIdx.x < 9) xs[threadIdx.x] = x[n * 9 + threadIdx.x];
    __syncthreads();
    int c = threadIdx.x;
    float acc = b[c];
#pragma unroll
    for (int k = 0; k < 9; k++) acc += xs[k] * W[k * HH + c];
    h[(size_t)n * HH + c] = acc;
}

// ---------------- LN+ReLU H=256 -> packed half2 hn (layer 1) -----------------
__global__ void ln_relu256p(const float* __restrict__ src, uint32_t* __restrict__ dsth,
                            const float* __restrict__ g, const float* __restrict__ b) {
    int warp = (blockIdx.x * blockDim.x + threadIdx.x) >> 5;
    int lane = threadIdx.x & 31;
    if (warp >= NN) return;
    const float* row = src + (size_t)warp * HH;
    float v[8];
    float s = 0.f, s2 = 0.f;
#pragma unroll
    for (int j = 0; j < 2; j++) {
        float4 t = *(const float4*)(row + j * 128 + lane * 4);
        v[j * 4 + 0] = t.x; v[j * 4 + 1] = t.y; v[j * 4 + 2] = t.z; v[j * 4 + 3] = t.w;
    }
#pragma unroll
    for (int j = 0; j < 8; j++) { s += v[j]; s2 += v[j] * v[j]; }
#pragma unroll
    for (int o = 16; o > 0; o >>= 1) {
        s += __shfl_xor_sync(0xffffffffu, s, o);
        s2 += __shfl_xor_sync(0xffffffffu, s2, o);
    }
    float mu = s / HH;
    float r = rsqrtf(s2 / HH - mu * mu + 1e-5f);
    uint32_t* orow = dsth + (size_t)warp * (HH / 2);
#pragma unroll
    for (int j = 0; j < 2; j++) {
        int c = j * 128 + lane * 4;
        float o0 = fmaxf((v[j * 4 + 0] - mu) * r * g[c + 0] + b[c + 0], 0.f);
        float o1 = fmaxf((v[j * 4 + 1] - mu) * r * g[c + 1] + b[c + 1], 0.f);
        float o2 = fmaxf((v[j * 4 + 2] - mu) * r * g[c + 2] + b[c + 2], 0.f);
        float o3 = fmaxf((v[j * 4 + 3] - mu) * r * g[c + 3] + b[c + 3], 0.f);
        uint2 w = make_uint2(pack_h2(o0, o1), pack_h2(o2, o3));
        *(uint2*)(orow + (c >> 1)) = w;
    }
}

// ---------- fused: h += vn[batch]; hn(packed) = relu(LN(h)) ------------------
__global__ void vn_ln_relu_p(float* __restrict__ h, uint32_t* __restrict__ hnh,
                             const float* __restrict__ vn, const int* __restrict__ batch,
                             const float* __restrict__ g, const float* __restrict__ b) {
    int warp = (blockIdx.x * blockDim.x + threadIdx.x) >> 5;
    int lane = threadIdx.x & 31;
    if (warp >= NN) return;
    float* row = h + (size_t)warp * HH;
    const float* vrow = vn + ((size_t)batch[warp] << 8);
    float v[8];
    float s = 0.f, s2 = 0.f;
#pragma unroll
    for (int j = 0; j < 2; j++) {
        int c = j * 128 + lane * 4;
        float4 t = *(const float4*)(row + c);
        float4 w = *(const float4*)(vrow + c);
        t.x += w.x; t.y += w.y; t.z += w.z; t.w += w.w;
        *(float4*)(row + c) = t;
        v[j * 4 + 0] = t.x; v[j * 4 + 1] = t.y; v[j * 4 + 2] = t.z; v[j * 4 + 3] = t.w;
    }
#pragma unroll
    for (int j = 0; j < 8; j++) { s += v[j]; s2 += v[j] * v[j]; }
#pragma unroll
    for (int o = 16; o > 0; o >>= 1) {
        s += __shfl_xor_sync(0xffffffffu, s, o);
        s2 += __shfl_xor_sync(0xffffffffu, s2, o);
    }
    float mu = s / HH;
    float r = rsqrtf(s2 / HH - mu * mu + 1e-5f);
    uint32_t* orow = hnh + (size_t)warp * (HH / 2);
#pragma unroll
    for (int j = 0; j < 2; j++) {
        int c = j * 128 + lane * 4;
        float o0 = fmaxf((v[j * 4 + 0] - mu) * r * g[c + 0] + b[c + 0], 0.f);
        float o1 = fmaxf((v[j * 4 + 1] - mu) * r * g[c + 1] + b[c + 1], 0.f);
        float o2 = fmaxf((v[j * 4 + 2] - mu) * r * g[c + 2] + b[c + 2], 0.f);
        float o3 = fmaxf((v[j * 4 + 3] - mu) * r * g[c + 3] + b[c + 3], 0.f);
        uint2 w = make_uint2(pack_h2(o0, o1), pack_h2(o2, o3));
        *(uint2*)(orow + (c >> 1)) = w;
    }
}

// ---------- final: h += vn[batch]; hn(fp32) = relu(LN(h)) --------------------
__global__ void vn_ln_relu_f(float* __restrict__ h, float* __restrict__ hn,
                             const float* __restrict__ vn, const int* __restrict__ batch,
                             const float* __restrict__ g, const float* __restrict__ b) {
    int warp = (blockIdx.x * blockDim.x + threadIdx.x) >> 5;
    int lane = threadIdx.x & 31;
    if (warp >= NN) return;
    float* row = h + (size_t)warp * HH;
    const float* vrow = vn + ((size_t)batch[warp] << 8);
    float v[8];
    float s = 0.f, s2 = 0.f;
#pragma unroll
    for (int j = 0; j < 2; j++) {
        int c = j * 128 + lane * 4;
        float4 t = *(const float4*)(row + c);
        float4 w = *(const float4*)(vrow + c);
        t.x += w.x; t.y += w.y; t.z += w.z; t.w += w.w;
        *(float4*)(row + c) = t;
        v[j * 4 + 0] = t.x; v[j * 4 + 1] = t.y; v[j * 4 + 2] = t.z; v[j * 4 + 3] = t.w;
    }
#pragma unroll
    for (int j = 0; j < 8; j++) { s += v[j]; s2 += v[j] * v[j]; }
#pragma unroll
    for (int o = 16; o > 0; o >>= 1) {
        s += __shfl_xor_sync(0xffffffffu, s, o);
        s2 += __shfl_xor_sync(0xffffffffu, s2, o);
    }
    float mu = s / HH;
    float r = rsqrtf(s2 / HH - mu * mu + 1e-5f);
    float* orow = hn + (size_t)warp * HH;
#pragma unroll
    for (int j = 0; j < 2; j++) {
        float4 o;
        int c = j * 128 + lane * 4;
        o.x = fmaxf((v[j * 4 + 0] - mu) * r * g[c + 0] + b[c + 0], 0.f);
        o.y = fmaxf((v[j * 4 + 1] - mu) * r * g[c + 1] + b[c + 1], 0.f);
        o.z = fmaxf((v[j * 4 + 2] - mu) * r * g[c + 2] + b[c + 2], 0.f);
        o.w = fmaxf((v[j * 4 + 3] - mu) * r * g[c + 3] + b[c + 3], 0.f);
        *(float4*)(orow + c) = o;
    }
}

// ------------- GENConv aggregation (packed hn in) -> half2 tmp ---------------
__global__ void aggregate(const uint32_t* __restrict__ hnh, const int* __restrict__ src,
                          const float* __restrict__ eattr, const float* __restrict__ eW,
                          const float* __restrict__ eb, const float* __restrict__ tptr,
                          uint32_t* __restrict__ outp) {
    __shared__ float sW[3 * HH];
    __shared__ float sb[HH];
    for (int i = threadIdx.x; i < 3 * HH; i += blockDim.x) sW[i] = eW[i];
    for (int i = threadIdx.x; i < HH; i += blockDim.x) sb[i] = eb[i];
    __syncthreads();
    int warp = blockIdx.x * (blockDim.x >> 5) + (threadIdx.x >> 5);
    int lane = threadIdx.x & 31;
    if (warp >= NN) return;
    float tval = *tptr;
    int e0 = g_indptr[warp], e1 = g_indptr[warp + 1];
    float m[8], d[8], a[8];
#pragma unroll
    for (int j = 0; j < 8; j++) { m[j] = -1e30f; d[j] = 0.f; a[j] = 0.f; }

    for (int e = e0; e < e1; e++) {
        int eid = g_csr[e];
        int u = src[eid];
        float e0a = eattr[eid * 3 + 0];
        float e1a = eattr[eid * 3 + 1];
        float e2a = eattr[eid * 3 + 2];
        const uint32_t* hrow = hnh + (size_t)u * (HH / 2);
#pragma unroll
        for (int gI = 0; gI < 2; gI++) {
            uint2 hu = *(const uint2*)(hrow + gI * 64 + lane * 2);
            float2 f0 = unpack_h2(hu.x);
            float2 f1 = unpack_h2(hu.y);
            float hvv[4] = {f0.x, f0.y, f1.x, f1.y};
#pragma unroll
            for (int q = 0; q < 4; q++) {
                int c = gI * 128 + lane * 4 + q;
                float ea = sb[c] + e0a * sW[c] + e1a * sW[HH + c] + e2a * sW[2 * HH + c];
                float msg = fmaxf(hvv[q] + ea, 0.f) + 1e-7f;
                float sc = msg * tval;
                int j = gI * 4 + q;
                float mn = fmaxf(m[j], sc);
                float em = __expf(m[j] - mn);
                float es = __expf(sc - mn);
                d[j] = d[j] * em + es;
                a[j] = a[j] * em + msg * es;
                m[j] = mn;
            }
        }
    }
    const uint32_t* hnrow = hnh + (size_t)warp * (HH / 2);
#pragma unroll
    for (int gI = 0; gI < 2; gI++) {
        uint2 hu = *(const uint2*)(hnrow + gI * 64 + lane * 2);
        float2 f0 = unpack_h2(hu.x);
        float2 f1 = unpack_h2(hu.y);
        float ox = a[gI * 4 + 0] / (d[gI * 4 + 0] + 1e-16f) + f0.x;
        float oy = a[gI * 4 + 1] / (d[gI * 4 + 1] + 1e-16f) + f0.y;
        float oz = a[gI * 4 + 2] / (d[gI * 4 + 2] + 1e-16f) + f1.x;
        float ow = a[gI * 4 + 3] / (d[gI * 4 + 3] + 1e-16f) + f1.y;
        int c0 = gI * 128 + lane * 4;
        uint2 w = make_uint2(pack_h2(ox, oy), pack_h2(oz, ow));
        *(uint2*)(outp + (size_t)warp * (HH / 2) + (c0 >> 1)) = w;
    }
}

// ------ GEMM1 (fp16 mma) + fused LN+ReLU epilogue -> half2 mid ---------------
// BM=64, BN=512 full row, 16 kpairs/tile. 8 warps, warp tile 64x64. (R14 exact)
__global__ __launch_bounds__(256) void gemm1_ln(
    const uint32_t* __restrict__ A, const uint32_t* __restrict__ Wh,
    const float* __restrict__ bias, const float* __restrict__ gam,
    const float* __restrict__ bet, uint32_t* __restrict__ mid, int M) {
    extern __shared__ char smraw[];
    typedef uint32_t AsT[64][20];
    typedef uint32_t BsT[16][520];
    AsT* As = (AsT*)smraw;
    BsT* Bs = (BsT*)(smraw + 2 * sizeof(AsT));
    const int KP = HH / 2, Nc = HB2, KT = KP >> 4;  // 8

    int tid = threadIdx.x;
    int lane = tid & 31, warp = tid >> 5;
    int wn = warp;
    int bm = blockIdx.x * 64;

    float acc[4][8][4];
#pragma unroll
    for (int mi = 0; mi < 4; mi++)
#pragma unroll
        for (int ni = 0; ni < 8; ni++)
#pragma unroll
            for (int q = 0; q < 4; q++) acc[mi][ni][q] = 0.f;

    auto load_stage = [&](int st, int kp0) {
        {
            int row = tid >> 2, c4 = tid & 3;
            int gr = bm + row;
            const uint32_t* srcp = A + (size_t)(gr < M ? gr : 0) * KP + kp0 + c4 * 4;
            uint32_t dst = (uint32_t)__cvta_generic_to_shared(&As[st][row][c4 * 4]);
            cp16(dst, srcp, (gr < M) ? 16 : 0);
        }
#pragma unroll
        for (int p = 0; p < 8; p++) {
            int cid = p * 256 + tid;
            int kr = cid >> 7, n4 = cid & 127;
            const uint32_t* srcp = Wh + (size_t)(kp0 + kr) * Nc + n4 * 4;
            uint32_t dst = (uint32_t)__cvta_generic_to_shared(&Bs[st][kr][n4 * 4]);
            cp16(dst, srcp, 16);
        }
    };

    load_stage(0, 0);
    cp_commit();

    for (int kt = 0; kt < KT; kt++) {
        if (kt + 1 < KT) {
            load_stage((kt + 1) & 1, (kt + 1) << 4);
            cp_commit();
            cp_wait<1>();
        } else {
            cp_wait<0>();
        }
        __syncthreads();
        int st = kt & 1;
#pragma unroll
        for (int k8 = 0; k8 < 16; k8 += 8) {
            int kk = k8 + (lane & 3);
            uint32_t af[4][4];
#pragma unroll
            for (int mi = 0; mi < 4; mi++) {
                int mr = mi * 16 + (lane >> 2);
                af[mi][0] = As[st][mr][kk];
                af[mi][1] = As[st][mr + 8][kk];
                af[mi][2] = As[st][mr][kk + 4];
                af[mi][3] = As[st][mr + 8][kk + 4];
            }
            uint32_t bf[8][2];
#pragma unroll
            for (int ni = 0; ni < 8; ni++) {
                int nc = wn * 64 + ni * 8 + (lane >> 2);
                bf[ni][0] = Bs[st][kk][nc];
                bf[ni][1] = Bs[st][kk + 4][nc];
            }
#pragma unroll
            for (int mi = 0; mi < 4; mi++)
#pragma unroll
                for (int ni = 0; ni < 8; ni++) mma_f16(acc[mi][ni], af[mi], bf[ni]);
        }
        __syncthreads();
    }

    // ---- epilogue: bias + row LayerNorm + ReLU -> half2 mid ----
    float* swsum = (float*)smraw;
    float* swsq = swsum + 512;
    float* smu = swsum + 1024;
    float* srv = swsum + 1088;
    float* sbias = (float*)(smraw + 2 * sizeof(AsT));
    float* sgam = sbias + 512;
    float* sbet = sbias + 1024;
    for (int i = tid; i < 512; i += 256) {
        sbias[i] = bias[i]; sgam[i] = gam[i]; sbet[i] = bet[i];
    }
    __syncthreads();

    float psum[8], psq[8];
#pragma unroll
    for (int mi = 0; mi < 4; mi++)
#pragma unroll
        for (int rr = 0; rr < 2; rr++) {
            int sidx = mi * 2 + rr;
            float s = 0.f, q2s = 0.f;
#pragma unroll
            for (int ni = 0; ni < 8; ni++)
#pragma unroll
                for (int q2 = 0; q2 < 2; q2++) {
                    int col = wn * 64 + ni * 8 + (lane & 3) * 2 + q2;
                    float v = acc[mi][ni][rr * 2 + q2] + sbias[col];
                    s += v; q2s += v * v;
                }
            psum[sidx] = s; psq[sidx] = q2s;
        }
#pragma unroll
    for (int sidx = 0; sidx < 8; sidx++) {
        psum[sidx] += __shfl_xor_sync(0xffffffffu, psum[sidx], 1);
        psum[sidx] += __shfl_xor_sync(0xffffffffu, psum[sidx], 2);
        psq[sidx] += __shfl_xor_sync(0xffffffffu, psq[sidx], 1);
        psq[sidx] += __shfl_xor_sync(0xffffffffu, psq[sidx], 2);
    }
    if ((lane & 3) == 0) {
#pragma unroll
        for (int mi = 0; mi < 4; mi++)
#pragma unroll
            for (int rr = 0; rr < 2; rr++) {
                int row = mi * 16 + (lane >> 2) + rr * 8;
                swsum[warp * 64 + row] = psum[mi * 2 + rr];
                swsq[warp * 64 + row] = psq[mi * 2 + rr];
            }
    }
    __syncthreads();
    if (tid < 64) {
        float s = 0.f, q = 0.f;
#pragma unroll
        for (int w = 0; w < 8; w++) { s += swsum[w * 64 + tid]; q += swsq[w * 64 + tid]; }
        float mu = s * (1.0f / HB2);
        float var = q * (1.0f / HB2) - mu * mu;
        smu[tid] = mu;
        srv[tid] = rsqrtf(var + 1e-5f);
    }
    __syncthreads();

#pragma unroll
    for (int mi = 0; mi < 4; mi++)
#pragma unroll
        for (int rr = 0; rr < 2; rr++) {
            int row = mi * 16 + (lane >> 2) + rr * 8;
            int grow = bm + row;
            if (grow >= M) continue;
            float mu = smu[row], rv = srv[row];
            uint32_t* orow = mid + (size_t)grow * (HB2 / 2);
#pragma unroll
            for (int ni = 0; ni < 8; ni++) {
                int col = wn * 64 + ni * 8 + (lane & 3) * 2;
                float v0 = acc[mi][ni][rr * 2 + 0] + sbias[col];
                float v1 = acc[mi][ni][rr * 2 + 1] + sbias[col + 1];
                float o0 = fmaxf((v0 - mu) * rv * sgam[col] + sbet[col], 0.f);
                float o1 = fmaxf((v1 - mu) * rv * sgam[col + 1] + sbet[col + 1], 0.f);
                orow[col >> 1] = pack_h2(o0, o1);
            }
        }
}

// ------ GEMM2 (fp16 mma): h += mid @ W2 + b2.  BM=128, BN=256 full row -------
// 8 warps (256 thr), warp tile 64x64. Single pass over mid (no N-split).
__global__ __launch_bounds__(256) void gemm2_full(
    const uint32_t* __restrict__ A, const uint32_t* __restrict__ Wh,
    const float* __restrict__ bias, float* __restrict__ C, int M) {
    extern __shared__ char smraw[];
    typedef uint32_t AsT[128][20];
    typedef uint32_t BsT[16][264];
    AsT* As = (AsT*)smraw;
    BsT* Bs = (BsT*)(smraw + 2 * sizeof(AsT));
    const int KP = HB2 / 2, Nc = HH, KT = KP >> 4;  // 16

    int tid = threadIdx.x;
    int lane = tid & 31, warp = tid >> 5;
    int wm = warp >> 2, wn = warp & 3;
    int bm = blockIdx.x * 128;

    float acc[4][8][4];
#pragma unroll
    for (int mi = 0; mi < 4; mi++)
#pragma unroll
        for (int ni = 0; ni < 8; ni++)
#pragma unroll
            for (int q = 0; q < 4; q++) acc[mi][ni][q] = 0.f;

    auto load_stage = [&](int st, int kp0) {
#pragma unroll
        for (int p = 0; p < 2; p++) {
            int cid = p * 256 + tid;
            int row = cid >> 2, c4 = cid & 3;
            int gr = bm + row;
            const uint32_t* srcp = A + (size_t)(gr < M ? gr : 0) * KP + kp0 + c4 * 4;
            uint32_t dst = (uint32_t)__cvta_generic_to_shared(&As[st][row][c4 * 4]);
            cp16(dst, srcp, (gr < M) ? 16 : 0);
        }
#pragma unroll
        for (int p = 0; p < 4; p++) {
            int cid = p * 256 + tid;
            int kr = cid >> 6, n4 = cid & 63;
            const uint32_t* srcp = Wh + (size_t)(kp0 + kr) * Nc + n4 * 4;
            uint32_t dst = (uint32_t)__cvta_generic_to_shared(&Bs[st][kr][n4 * 4]);
            cp16(dst, srcp, 16);
        }
    };

    load_stage(0, 0);
    cp_commit();

    for (int kt = 0; kt < KT; kt++) {
        if (kt + 1 < KT) {
            load_stage((kt + 1) & 1, (kt + 1) << 4);
            cp_commit();
            cp_wait<1>();
        } else {
            cp_wait<0>();
        }
        __syncthreads();
        int st = kt & 1;
#pragma unroll
        for (int k8 = 0; k8 < 16; k8 += 8) {
            int kk = k8 + (lane & 3);
            uint32_t af[4][4];
#pragma unroll
            for (int mi = 0; mi < 4; mi++) {
                int mr = wm * 64 + mi * 16 + (lane >> 2);
                af[mi][0] = As[st][mr][kk];
                af[mi][1] = As[st][mr + 8][kk];
                af[mi][2] = As[st][mr][kk + 4];
                af[mi][3] = As[st][mr + 8][kk + 4];
            }
            uint32_t bf[8][2];
#pragma unroll
            for (int ni = 0; ni < 8; ni++) {
                int nc = wn * 64 + ni * 8 + (lane >> 2);
                bf[ni][0] = Bs[st][kk][nc];
                bf[ni][1] = Bs[st][kk + 4][nc];
            }
#pragma unroll
            for (int mi = 0; mi < 4; mi++)
#pragma unroll
                for (int ni = 0; ni < 8; ni++) mma_f16(acc[mi][ni], af[mi], bf[ni]);
        }
        __syncthreads();
    }
#pragma unroll
    for (int mi = 0; mi < 4; mi++) {
#pragma unroll
        for (int rr = 0; rr < 2; rr++) {
            int row = bm + wm * 64 + mi * 16 + (lane >> 2) + rr * 8;
            if (row >= M) continue;
#pragma unroll
            for (int ni = 0; ni < 8; ni++) {
                int col = wn * 64 + ni * 8 + (lane & 3) * 2;
                float* p = C + (size_t)row * Nc + col;
                float2 v;
                v.x = acc[mi][ni][rr * 2 + 0] + bias[col] + p[0];
                v.y = acc[mi][ni][rr * 2 + 1] + bias[col + 1] + p[1];
                *(float2*)p = v;
            }
        }
    }
}

// ------------- pooling over sorted batch -------------------------------------
__global__ void pool_sum(const float* __restrict__ src, const int* __restrict__ batch,
                         float* __restrict__ out) {
    __shared__ int sb[512];
    int n0 = blockIdx.x * 512;
    int nend = min(n0 + 512, NN);
    for (int i = threadIdx.x; i < nend - n0; i += 256) sb[i] = batch[n0 + i];
    __syncthreads();
    int c = threadIdx.x;
    float acc = 0.f;
    int cur = sb[0];
    for (int n = n0; n < nend; n++) {
        int b = sb[n - n0];
        if (b != cur) {
            atomicAdd(&out[(size_t)cur * HH + c], acc);
            acc = 0.f;
            cur = b;
        }
        acc += src[(size_t)n * HH + c];
    }
    atomicAdd(&out[(size_t)cur * HH + c], acc);
}

// vn += vnsum*inv, then zero vnsum for next layer (saves a zero_f pass)
__global__ void vn_update(float* __restrict__ vn, float* __restrict__ vnsum,
                          const float* __restrict__ inv) {
    int i = blockIdx.x * blockDim.x + threadIdx.x;
    if (i < BBATCH * HH) {
        vn[i] += vnsum[i] * inv[i >> 8];
        vnsum[i] = 0.f;
    }
}

__global__ void scale_out(float* __restrict__ out, const float* __restrict__ inv) {
    int i = blockIdx.x * blockDim.x + threadIdx.x;
    if (i < BBATCH * HH) out[i] *= inv[i >> 8];
}

// ------------------------------ host orchestration ---------------------------
extern "C" void kernel_launch(void* const* d_in, const int* in_sizes, int n_in,
                              void* d_out, int out_size) {
    const float* x = (const float*)d_in[0];
    const int* eidx = (const int*)d_in[1];
    const float* eattr = (const float*)d_in[2];
    const int* batch = (const int*)d_in[3];
    const float* node_W = (const float*)d_in[4];
    const float* node_b = (const float*)d_in[5];
    const float* edge_W = (const float*)d_in[6];
    const float* edge_b = (const float*)d_in[7];
    const float* vn_emb = (const float*)d_in[8];
    const float* ln_g = (const float*)d_in[9];
    const float* ln_b = (const float*)d_in[10];
    const float* tt = (const float*)d_in[11];
    const float* W1 = (const float*)d_in[12];
    const float* b1 = (const float*)d_in[13];
    const float* mg = (const float*)d_in[14];
    const float* mb = (const float*)d_in[15];
    const float* W2 = (const float*)d_in[16];
    const float* b2 = (const float*)d_in[17];
    float* out = (float*)d_out;
    const int* srcp = eidx;
    const int* dstp = eidx + EE;

    float *h_, *hn_, *vn_, *vnsum_, *inv_;
    uint32_t *hnh_, *tmph_, *midh_, *w1h_, *w2h_;
    cudaGetSymbolAddress((void**)&h_, g_h);
    cudaGetSymbolAddress((void**)&hn_, g_hn);
    cudaGetSymbolAddress((void**)&hnh_, g_hnh);
    cudaGetSymbolAddress((void**)&tmph_, g_tmph);
    cudaGetSymbolAddress((void**)&midh_, g_midh);
    cudaGetSymbolAddress((void**)&vn_, g_vn);
    cudaGetSymbolAddress((void**)&vnsum_, g_vnsum);
    cudaGetSymbolAddress((void**)&inv_, g_inv);
    cudaGetSymbolAddress((void**)&w1h_, g_w1h);
    cudaGetSymbolAddress((void**)&w2h_, g_w2h);

    const int NB_SCAN = (NN + 1023) / 1024;
    const int NW = (HH / 2) * HB2;
    const int SMEM1 = 2 * (64 * 20 + 16 * 520) * 4;   // 76800
    const int SMEM2 = 2 * (128 * 20 + 16 * 264) * 4;  // 54272

    cudaFuncSetAttribute(gemm1_ln, cudaFuncAttributeMaxDynamicSharedMemorySize, SMEM1);
    cudaFuncSetAttribute(gemm2_full, cudaFuncAttributeMaxDynamicSharedMemorySize, SMEM2);

    // ---- setup ----
    zero_setup<<<(NN + 255) / 256, 256>>>();
    count_deg<<<(EE + 255) / 256, 256>>>(dstp);
    count_batch<<<(NN + 255) / 256, 256>>>(batch);
    scan_block<<<NB_SCAN, 1024>>>();
    scan_sums<<<1, 128>>>(NB_SCAN);
    add_offs<<<(NN + 255) / 256, 256>>>();
    csr_fill<<<(EE + 255) / 256, 256>>>(dstp);
    calc_inv<<<(BBATCH + 255) / 256, 256>>>();
    vn_init<<<(BBATCH * HH + 255) / 256, 256>>>(vn_, vn_emb);
    zero_f<<<(BBATCH * HH + 255) / 256, 256>>>(vnsum_, BBATCH * HH);
    for (int l = 0; l < 3; l++) {
        packWh<<<(NW + 255) / 256, 256>>>(W1 + (size_t)l * HH * HB2, w1h_ + (size_t)l * NW,
                                          HH, HB2);
        packWh<<<(NW + 255) / 256, 256>>>(W2 + (size_t)l * HB2 * HH, w2h_ + (size_t)l * NW,
                                          HB2, HH);
    }
    node_enc<<<NN, 256>>>(x, node_W, node_b, h_);

    // ---- layers 1..3 ----
    for (int l = 1; l < LLAYERS; l++) {
        if (l == 1)
            ln_relu256p<<<NN / 8, 256>>>(h_, hnh_, ln_g + l * HH, ln_b + l * HH);
        else
            vn_ln_relu_p<<<NN / 8, 256>>>(h_, hnh_, vn_, batch, ln_g + l * HH, ln_b + l * HH);
        aggregate<<<NN / 8, 256>>>(hnh_, srcp, eattr, edge_W, edge_b, tt + (l - 1), tmph_);
        gemm1_ln<<<(NN + 63) / 64, 256, SMEM1>>>(
            tmph_, w1h_ + (size_t)(l - 1) * NW, b1 + (l - 1) * HB2,
            mg + (l - 1) * HB2, mb + (l - 1) * HB2, midh_, NN);
        gemm2_full<<<(NN + 127) / 128, 256, SMEM2>>>(
            midh_, w2h_ + (size_t)(l - 1) * NW, b2 + (l - 1) * HH, h_, NN);
        pool_sum<<<(NN + 511) / 512, 256>>>(h_, batch, vnsum_);
        vn_update<<<(BBATCH * HH + 255) / 256, 256>>>(vn_, vnsum_, inv_);
    }

    // ---- final ----
    vn_ln_relu_f<<<NN / 8, 256>>>(h_, hn_, vn_, batch, ln_g, ln_b);
    zero_f<<<(BBATCH * HH + 255) / 256, 256>>>(out, BBATCH * HH);
    pool_sum<<<(NN + 511) / 512, 256>>>(hn_, batch, out);
    scale_out<<<(BBATCH * HH + 255) / 256, 256>>>(out, inv_);
}

// round 17
// speedup vs baseline: 1.0958x; 1.0958x over previous
#include <cuda_runtime.h>
#include <cuda_fp16.h>
#include <cstdint>

#define NN 100000
#define EE 200000
#define BBATCH 2048
#define HH 256
#define HB2 512
#define LLAYERS 4

// ------------------------- scratch (device globals; no allocs) ---------------
__device__ float g_h[(size_t)NN * HH];
__device__ float g_hn[(size_t)NN * HH];             // fp32 hn (final layer only)
__device__ uint32_t g_hnh[(size_t)NN * (HH / 2)];   // half2-packed hn (layers)
__device__ uint32_t g_tmph[(size_t)NN * (HH / 2)];  // half2-packed A for GEMM1
__device__ uint32_t g_midh[(size_t)NN * (HB2 / 2)]; // half2-packed A for GEMM2
__device__ uint32_t g_w1h[3 * (HH / 2) * HB2];      // [kp][n] packed W1
__device__ uint32_t g_w2h[3 * (HB2 / 2) * HH];      // [kp][n] packed W2
__device__ float g_vn[BBATCH * HH];
__device__ float g_vnsum[BBATCH * HH];
__device__ float g_inv[BBATCH];
__device__ int g_deg[NN];
__device__ int g_indptr[NN + 1];
__device__ int g_cursor[NN];
__device__ int g_csr[EE];
__device__ int g_cnt[BBATCH];
__device__ int g_bsums[128];
__device__ int g_boffs[128];

// ------------------------- small helpers -------------------------------------
__device__ __forceinline__ uint32_t pack_h2(float a, float b) {
    __half2 h = __floats2half2_rn(a, b);
    return *reinterpret_cast<uint32_t*>(&h);
}
__device__ __forceinline__ float2 unpack_h2(uint32_t u) {
    return __half22float2(*reinterpret_cast<__half2*>(&u));
}

__device__ __forceinline__ void mma_f16(float* c, const uint32_t* a, const uint32_t* b) {
    asm volatile(
        "mma.sync.aligned.m16n8k16.row.col.f32.f16.f16.f32 "
        "{%0,%1,%2,%3},{%4,%5,%6,%7},{%8,%9},{%0,%1,%2,%3};"
        : "+f"(c[0]), "+f"(c[1]), "+f"(c[2]), "+f"(c[3])
        : "r"(a[0]), "r"(a[1]), "r"(a[2]), "r"(a[3]), "r"(b[0]), "r"(b[1]));
}

__device__ __forceinline__ void cp16(uint32_t dst, const void* src, int bytes) {
    asm volatile("cp.async.cg.shared.global [%0], [%1], 16, %2;\n" ::"r"(dst), "l"(src),
                 "r"(bytes));
}
__device__ __forceinline__ void cp_commit() { asm volatile("cp.async.commit_group;\n"); }
template <int W>
__device__ __forceinline__ void cp_wait() {
    asm volatile("cp.async.wait_group %0;\n" ::"n"(W));
}

// ------------------------- setup kernels -------------------------------------
__global__ void zero_setup() {
    int i = blockIdx.x * blockDim.x + threadIdx.x;
    if (i < NN) { g_deg[i] = 0; g_cursor[i] = 0; }
    if (i < BBATCH) g_cnt[i] = 0;
}

__global__ void zero_f(float* p, int n) {
    int i = blockIdx.x * blockDim.x + threadIdx.x;
    if (i < n) p[i] = 0.0f;
}

__global__ void count_deg(const int* __restrict__ dst) {
    int e = blockIdx.x * blockDim.x + threadIdx.x;
    if (e < EE) atomicAdd(&g_deg[dst[e]], 1);
}

__global__ void count_batch(const int* __restrict__ batch) {
    int n = blockIdx.x * blockDim.x + threadIdx.x;
    if (n < NN) atomicAdd(&g_cnt[batch[n]], 1);
}

__global__ void scan_block() {
    __shared__ int s[1024];
    int i = blockIdx.x * 1024 + threadIdx.x;
    int v = (i < NN) ? g_deg[i] : 0;
    s[threadIdx.x] = v;
    __syncthreads();
#pragma unroll
    for (int off = 1; off < 1024; off <<= 1) {
        int t = (threadIdx.x >= off) ? s[threadIdx.x - off] : 0;
        __syncthreads();
        s[threadIdx.x] += t;
        __syncthreads();
    }
    if (i < NN) g_indptr[i + 1] = s[threadIdx.x];
    if (threadIdx.x == 1023) g_bsums[blockIdx.x] = s[1023];
    if (i == 0) g_indptr[0] = 0;
}

__global__ void scan_sums(int nb) {
    __shared__ int s[128];
    int t = threadIdx.x;
    int v = (t < nb) ? g_bsums[t] : 0;
    s[t] = v;
    __syncthreads();
#pragma unroll
    for (int off = 1; off < 128; off <<= 1) {
        int u = (t >= off) ? s[t - off] : 0;
        __syncthreads();
        s[t] += u;
        __syncthreads();
    }
    if (t < nb) g_boffs[t] = s[t] - v;
}

__global__ void add_offs() {
    int i = blockIdx.x * blockDim.x + threadIdx.x;
    if (i < NN) g_indptr[i + 1] += g_boffs[i >> 10];
}

__global__ void csr_fill(const int* __restrict__ dst) {
    int e = blockIdx.x * blockDim.x + threadIdx.x;
    if (e < EE) {
        int d = dst[e];
        int p = atomicAdd(&g_cursor[d], 1);
        g_csr[g_indptr[d] + p] = e;
    }
}

__global__ void calc_inv() {
    int b = blockIdx.x * blockDim.x + threadIdx.x;
    if (b < BBATCH) g_inv[b] = 1.0f / fmaxf((float)g_cnt[b], 1.0f);
}

__global__ void vn_init(float* __restrict__ vn, const float* __restrict__ emb) {
    int i = blockIdx.x * blockDim.x + threadIdx.x;
    if (i < BBATCH * HH) vn[i] = emb[i & (HH - 1)];
}

// pack W[K][N] fp32 -> [K/2][N] u32 (half2 along k)
__global__ void packWh(const float* __restrict__ W, uint32_t* __restrict__ o, int K, int N) {
    int i = blockIdx.x * blockDim.x + threadIdx.x;
    int tot = (K / 2) * N;
    if (i >= tot) return;
    int kp = i / N, n = i % N;
    o[i] = pack_h2(W[(2 * kp) * N + n], W[(2 * kp + 1) * N + n]);
}

// ------------------------- node encoder -------------------------------------
__global__ void node_enc(const float* __restrict__ x, const float* __restrict__ W,
                         const float* __restrict__ b, float* __restrict__ h) {
    __shared__ float xs[9];
    int n = blockIdx.x;
    if (threadIdx.x < 9) xs[threadIdx.x] = x[n * 9 + threadIdx.x];
    __syncthreads();
    int c = threadIdx.x;
    float acc = b[c];
#pragma unroll
    for (int k = 0; k < 9; k++) acc += xs[k] * W[k * HH + c];
    h[(size_t)n * HH + c] = acc;
}

// ---------------- LN+ReLU H=256 -> packed half2 hn (layer 1) -----------------
__global__ void ln_relu256p(const float* __restrict__ src, uint32_t* __restrict__ dsth,
                            const float* __restrict__ g, const float* __restrict__ b) {
    int warp = (blockIdx.x * blockDim.x + threadIdx.x) >> 5;
    int lane = threadIdx.x & 31;
    if (warp >= NN) return;
    const float* row = src + (size_t)warp * HH;
    float v[8];
    float s = 0.f, s2 = 0.f;
#pragma unroll
    for (int j = 0; j < 2; j++) {
        float4 t = *(const float4*)(row + j * 128 + lane * 4);
        v[j * 4 + 0] = t.x; v[j * 4 + 1] = t.y; v[j * 4 + 2] = t.z; v[j * 4 + 3] = t.w;
    }
#pragma unroll
    for (int j = 0; j < 8; j++) { s += v[j]; s2 += v[j] * v[j]; }
#pragma unroll
    for (int o = 16; o > 0; o >>= 1) {
        s += __shfl_xor_sync(0xffffffffu, s, o);
        s2 += __shfl_xor_sync(0xffffffffu, s2, o);
    }
    float mu = s / HH;
    float r = rsqrtf(s2 / HH - mu * mu + 1e-5f);
    uint32_t* orow = dsth + (size_t)warp * (HH / 2);
#pragma unroll
    for (int j = 0; j < 2; j++) {
        int c = j * 128 + lane * 4;
        float o0 = fmaxf((v[j * 4 + 0] - mu) * r * g[c + 0] + b[c + 0], 0.f);
        float o1 = fmaxf((v[j * 4 + 1] - mu) * r * g[c + 1] + b[c + 1], 0.f);
        float o2 = fmaxf((v[j * 4 + 2] - mu) * r * g[c + 2] + b[c + 2], 0.f);
        float o3 = fmaxf((v[j * 4 + 3] - mu) * r * g[c + 3] + b[c + 3], 0.f);
        uint2 w = make_uint2(pack_h2(o0, o1), pack_h2(o2, o3));
        *(uint2*)(orow + (c >> 1)) = w;
    }
}

// ---------- fused: h += vn[batch]; hn(packed) = relu(LN(h)) ------------------
__global__ void vn_ln_relu_p(float* __restrict__ h, uint32_t* __restrict__ hnh,
                             const float* __restrict__ vn, const int* __restrict__ batch,
                             const float* __restrict__ g, const float* __restrict__ b) {
    int warp = (blockIdx.x * blockDim.x + threadIdx.x) >> 5;
    int lane = threadIdx.x & 31;
    if (warp >= NN) return;
    float* row = h + (size_t)warp * HH;
    const float* vrow = vn + ((size_t)batch[warp] << 8);
    float v[8];
    float s = 0.f, s2 = 0.f;
#pragma unroll
    for (int j = 0; j < 2; j++) {
        int c = j * 128 + lane * 4;
        float4 t = *(const float4*)(row + c);
        float4 w = *(const float4*)(vrow + c);
        t.x += w.x; t.y += w.y; t.z += w.z; t.w += w.w;
        *(float4*)(row + c) = t;
        v[j * 4 + 0] = t.x; v[j * 4 + 1] = t.y; v[j * 4 + 2] = t.z; v[j * 4 + 3] = t.w;
    }
#pragma unroll
    for (int j = 0; j < 8; j++) { s += v[j]; s2 += v[j] * v[j]; }
#pragma unroll
    for (int o = 16; o > 0; o >>= 1) {
        s += __shfl_xor_sync(0xffffffffu, s, o);
        s2 += __shfl_xor_sync(0xffffffffu, s2, o);
    }
    float mu = s / HH;
    float r = rsqrtf(s2 / HH - mu * mu + 1e-5f);
    uint32_t* orow = hnh + (size_t)warp * (HH / 2);
#pragma unroll
    for (int j = 0; j < 2; j++) {
        int c = j * 128 + lane * 4;
        float o0 = fmaxf((v[j * 4 + 0] - mu) * r * g[c + 0] + b[c + 0], 0.f);
        float o1 = fmaxf((v[j * 4 + 1] - mu) * r * g[c + 1] + b[c + 1], 0.f);
        float o2 = fmaxf((v[j * 4 + 2] - mu) * r * g[c + 2] + b[c + 2], 0.f);
        float o3 = fmaxf((v[j * 4 + 3] - mu) * r * g[c + 3] + b[c + 3], 0.f);
        uint2 w = make_uint2(pack_h2(o0, o1), pack_h2(o2, o3));
        *(uint2*)(orow + (c >> 1)) = w;
    }
}

// ---------- final: h += vn[batch]; hn(fp32) = relu(LN(h)) --------------------
__global__ void vn_ln_relu_f(float* __restrict__ h, float* __restrict__ hn,
                             const float* __restrict__ vn, const int* __restrict__ batch,
                             const float* __restrict__ g, const float* __restrict__ b) {
    int warp = (blockIdx.x * blockDim.x + threadIdx.x) >> 5;
    int lane = threadIdx.x & 31;
    if (warp >= NN) return;
    float* row = h + (size_t)warp * HH;
    const float* vrow = vn + ((size_t)batch[warp] << 8);
    float v[8];
    float s = 0.f, s2 = 0.f;
#pragma unroll
    for (int j = 0; j < 2; j++) {
        int c = j * 128 + lane * 4;
        float4 t = *(const float4*)(row + c);
        float4 w = *(const float4*)(vrow + c);
        t.x += w.x; t.y += w.y; t.z += w.z; t.w += w.w;
        *(float4*)(row + c) = t;
        v[j * 4 + 0] = t.x; v[j * 4 + 1] = t.y; v[j * 4 + 2] = t.z; v[j * 4 + 3] = t.w;
    }
#pragma unroll
    for (int j = 0; j < 8; j++) { s += v[j]; s2 += v[j] * v[j]; }
#pragma unroll
    for (int o = 16; o > 0; o >>= 1) {
        s += __shfl_xor_sync(0xffffffffu, s, o);
        s2 += __shfl_xor_sync(0xffffffffu, s2, o);
    }
    float mu = s / HH;
    float r = rsqrtf(s2 / HH - mu * mu + 1e-5f);
    float* orow = hn + (size_t)warp * HH;
#pragma unroll
    for (int j = 0; j < 2; j++) {
        float4 o;
        int c = j * 128 + lane * 4;
        o.x = fmaxf((v[j * 4 + 0] - mu) * r * g[c + 0] + b[c + 0], 0.f);
        o.y = fmaxf((v[j * 4 + 1] - mu) * r * g[c + 1] + b[c + 1], 0.f);
        o.z = fmaxf((v[j * 4 + 2] - mu) * r * g[c + 2] + b[c + 2], 0.f);
        o.w = fmaxf((v[j * 4 + 3] - mu) * r * g[c + 3] + b[c + 3], 0.f);
        *(float4*)(orow + c) = o;
    }
}

// ------------- GENConv aggregation (packed hn in) -> half2 tmp ---------------
__global__ void aggregate(const uint32_t* __restrict__ hnh, const int* __restrict__ src,
                          const float* __restrict__ eattr, const float* __restrict__ eW,
                          const float* __restrict__ eb, const float* __restrict__ tptr,
                          uint32_t* __restrict__ outp) {
    __shared__ float sW[3 * HH];
    __shared__ float sb[HH];
    for (int i = threadIdx.x; i < 3 * HH; i += blockDim.x) sW[i] = eW[i];
    for (int i = threadIdx.x; i < HH; i += blockDim.x) sb[i] = eb[i];
    __syncthreads();
    int warp = blockIdx.x * (blockDim.x >> 5) + (threadIdx.x >> 5);
    int lane = threadIdx.x & 31;
    if (warp >= NN) return;
    float tval = *tptr;
    int e0 = g_indptr[warp], e1 = g_indptr[warp + 1];
    float m[8], d[8], a[8];
#pragma unroll
    for (int j = 0; j < 8; j++) { m[j] = -1e30f; d[j] = 0.f; a[j] = 0.f; }

    for (int e = e0; e < e1; e++) {
        int eid = g_csr[e];
        int u = src[eid];
        float e0a = eattr[eid * 3 + 0];
        float e1a = eattr[eid * 3 + 1];
        float e2a = eattr[eid * 3 + 2];
        const uint32_t* hrow = hnh + (size_t)u * (HH / 2);
#pragma unroll
        for (int gI = 0; gI < 2; gI++) {
            uint2 hu = *(const uint2*)(hrow + gI * 64 + lane * 2);
            float2 f0 = unpack_h2(hu.x);
            float2 f1 = unpack_h2(hu.y);
            float hvv[4] = {f0.x, f0.y, f1.x, f1.y};
#pragma unroll
            for (int q = 0; q < 4; q++) {
                int c = gI * 128 + lane * 4 + q;
                float ea = sb[c] + e0a * sW[c] + e1a * sW[HH + c] + e2a * sW[2 * HH + c];
                float msg = fmaxf(hvv[q] + ea, 0.f) + 1e-7f;
                float sc = msg * tval;
                int j = gI * 4 + q;
                float mn = fmaxf(m[j], sc);
                float em = __expf(m[j] - mn);
                float es = __expf(sc - mn);
                d[j] = d[j] * em + es;
                a[j] = a[j] * em + msg * es;
                m[j] = mn;
            }
        }
    }
    const uint32_t* hnrow = hnh + (size_t)warp * (HH / 2);
#pragma unroll
    for (int gI = 0; gI < 2; gI++) {
        uint2 hu = *(const uint2*)(hnrow + gI * 64 + lane * 2);
        float2 f0 = unpack_h2(hu.x);
        float2 f1 = unpack_h2(hu.y);
        float ox = a[gI * 4 + 0] / (d[gI * 4 + 0] + 1e-16f) + f0.x;
        float oy = a[gI * 4 + 1] / (d[gI * 4 + 1] + 1e-16f) + f0.y;
        float oz = a[gI * 4 + 2] / (d[gI * 4 + 2] + 1e-16f) + f1.x;
        float ow = a[gI * 4 + 3] / (d[gI * 4 + 3] + 1e-16f) + f1.y;
        int c0 = gI * 128 + lane * 4;
        uint2 w = make_uint2(pack_h2(ox, oy), pack_h2(oz, ow));
        *(uint2*)(outp + (size_t)warp * (HH / 2) + (c0 >> 1)) = w;
    }
}

// ------ GEMM1 (fp16 mma) + fused LN+ReLU epilogue -> half2 mid ---------------
// BM=32, BN=512 full row. 8 warps, warp tile 32x64 -> 64 acc regs/thread,
// __launch_bounds__(256,2) => 2 blocks/SM (16 warps) for latency hiding.
__global__ __launch_bounds__(256, 2) void gemm1_ln(
    const uint32_t* __restrict__ A, const uint32_t* __restrict__ Wh,
    const float* __restrict__ bias, const float* __restrict__ gam,
    const float* __restrict__ bet, uint32_t* __restrict__ mid, int M) {
    extern __shared__ char smraw[];
    typedef uint32_t AsT[32][20];
    typedef uint32_t BsT[16][520];
    AsT* As = (AsT*)smraw;                         // 2 * 2560 B
    BsT* Bs = (BsT*)(smraw + 2 * sizeof(AsT));     // 2 * 33280 B
    const int KP = HH / 2, Nc = HB2, KT = KP >> 4; // 8

    int tid = threadIdx.x;
    int lane = tid & 31, warp = tid >> 5;
    int wn = warp;
    int bm = blockIdx.x * 32;

    float acc[2][8][4];
#pragma unroll
    for (int mi = 0; mi < 2; mi++)
#pragma unroll
        for (int ni = 0; ni < 8; ni++)
#pragma unroll
            for (int q = 0; q < 4; q++) acc[mi][ni][q] = 0.f;

    auto load_stage = [&](int st, int kp0) {
        if (tid < 128) {
            int row = tid >> 2, c4 = tid & 3;
            int gr = bm + row;
            const uint32_t* srcp = A + (size_t)(gr < M ? gr : 0) * KP + kp0 + c4 * 4;
            uint32_t dst = (uint32_t)__cvta_generic_to_shared(&As[st][row][c4 * 4]);
            cp16(dst, srcp, (gr < M) ? 16 : 0);
        }
#pragma unroll
        for (int p = 0; p < 8; p++) {
            int cid = p * 256 + tid;
            int kr = cid >> 7, n4 = cid & 127;
            const uint32_t* srcp = Wh + (size_t)(kp0 + kr) * Nc + n4 * 4;
            uint32_t dst = (uint32_t)__cvta_generic_to_shared(&Bs[st][kr][n4 * 4]);
            cp16(dst, srcp, 16);
        }
    };

    load_stage(0, 0);
    cp_commit();

    for (int kt = 0; kt < KT; kt++) {
        if (kt + 1 < KT) {
            load_stage((kt + 1) & 1, (kt + 1) << 4);
            cp_commit();
            cp_wait<1>();
        } else {
            cp_wait<0>();
        }
        __syncthreads();
        int st = kt & 1;
#pragma unroll
        for (int k8 = 0; k8 < 16; k8 += 8) {
            int kk = k8 + (lane & 3);
            uint32_t af[2][4];
#pragma unroll
            for (int mi = 0; mi < 2; mi++) {
                int mr = mi * 16 + (lane >> 2);
                af[mi][0] = As[st][mr][kk];
                af[mi][1] = As[st][mr + 8][kk];
                af[mi][2] = As[st][mr][kk + 4];
                af[mi][3] = As[st][mr + 8][kk + 4];
            }
            uint32_t bf[8][2];
#pragma unroll
            for (int ni = 0; ni < 8; ni++) {
                int nc = wn * 64 + ni * 8 + (lane >> 2);
                bf[ni][0] = Bs[st][kk][nc];
                bf[ni][1] = Bs[st][kk + 4][nc];
            }
#pragma unroll
            for (int mi = 0; mi < 2; mi++)
#pragma unroll
                for (int ni = 0; ni < 8; ni++) mma_f16(acc[mi][ni], af[mi], bf[ni]);
        }
        __syncthreads();
    }

    // ---- epilogue: bias + row LayerNorm + ReLU -> half2 mid ----
    float* swsum = (float*)smraw;                      // [8][32]
    float* swsq = swsum + 256;                         // [8][32]
    float* smu = swsum + 512;                          // [32]
    float* srv = swsum + 544;                          // [32]
    float* sbias = (float*)(smraw + 2 * sizeof(AsT));  // [512] in Bs region
    float* sgam = sbias + 512;
    float* sbet = sbias + 1024;
    for (int i = tid; i < 512; i += 256) {
        sbias[i] = bias[i]; sgam[i] = gam[i]; sbet[i] = bet[i];
    }
    __syncthreads();

    float psum[4], psq[4];
#pragma unroll
    for (int mi = 0; mi < 2; mi++)
#pragma unroll
        for (int rr = 0; rr < 2; rr++) {
            int sidx = mi * 2 + rr;
            float s = 0.f, q2s = 0.f;
#pragma unroll
            for (int ni = 0; ni < 8; ni++)
#pragma unroll
                for (int q2 = 0; q2 < 2; q2++) {
                    int col = wn * 64 + ni * 8 + (lane & 3) * 2 + q2;
                    float v = acc[mi][ni][rr * 2 + q2] + sbias[col];
                    s += v; q2s += v * v;
                }
            psum[sidx] = s; psq[sidx] = q2s;
        }
#pragma unroll
    for (int sidx = 0; sidx < 4; sidx++) {
        psum[sidx] += __shfl_xor_sync(0xffffffffu, psum[sidx], 1);
        psum[sidx] += __shfl_xor_sync(0xffffffffu, psum[sidx], 2);
        psq[sidx] += __shfl_xor_sync(0xffffffffu, psq[sidx], 1);
        psq[sidx] += __shfl_xor_sync(0xffffffffu, psq[sidx], 2);
    }
    if ((lane & 3) == 0) {
#pragma unroll
        for (int mi = 0; mi < 2; mi++)
#pragma unroll
            for (int rr = 0; rr < 2; rr++) {
                int row = mi * 16 + (lane >> 2) + rr * 8;
                swsum[warp * 32 + row] = psum[mi * 2 + rr];
                swsq[warp * 32 + row] = psq[mi * 2 + rr];
            }
    }
    __syncthreads();
    if (tid < 32) {
        float s = 0.f, q = 0.f;
#pragma unroll
        for (int w = 0; w < 8; w++) { s += swsum[w * 32 + tid]; q += swsq[w * 32 + tid]; }
        float mu = s * (1.0f / HB2);
        float var = q * (1.0f / HB2) - mu * mu;
        smu[tid] = mu;
        srv[tid] = rsqrtf(var + 1e-5f);
    }
    __syncthreads();

#pragma unroll
    for (int mi = 0; mi < 2; mi++)
#pragma unroll
        for (int rr = 0; rr < 2; rr++) {
            int row = mi * 16 + (lane >> 2) + rr * 8;
            int grow = bm + row;
            if (grow >= M) continue;
            float mu = smu[row], rv = srv[row];
            uint32_t* orow = mid + (size_t)grow * (HB2 / 2);
#pragma unroll
            for (int ni = 0; ni < 8; ni++) {
                int col = wn * 64 + ni * 8 + (lane & 3) * 2;
                float v0 = acc[mi][ni][rr * 2 + 0] + sbias[col];
                float v1 = acc[mi][ni][rr * 2 + 1] + sbias[col + 1];
                float o0 = fmaxf((v0 - mu) * rv * sgam[col] + sbet[col], 0.f);
                float o1 = fmaxf((v1 - mu) * rv * sgam[col + 1] + sbet[col + 1], 0.f);
                orow[col >> 1] = pack_h2(o0, o1);
            }
        }
}

// ------ GEMM2 (fp16 mma): h += mid @ W2 + b2.  BM=128 BN=128 (R14 exact) -----
__global__ __launch_bounds__(128) void gemm2_pipe(
    const uint32_t* __restrict__ A, const uint32_t* __restrict__ Wh,
    const float* __restrict__ bias, float* __restrict__ C, int M) {
    extern __shared__ char smraw[];
    typedef uint32_t AsT[128][20];
    typedef uint32_t BsT[16][136];
    AsT* As = (AsT*)smraw;
    BsT* Bs = (BsT*)(smraw + 2 * sizeof(AsT));
    const int KP = HB2 / 2, Nc = HH, KT = KP >> 4;  // 16

    int tid = threadIdx.x;
    int lane = tid & 31, warp = tid >> 5;
    int wm = warp >> 1, wn = warp & 1;
    int bm = blockIdx.y * 128, bn = blockIdx.x * 128;

    float acc[4][8][4];
#pragma unroll
    for (int mi = 0; mi < 4; mi++)
#pragma unroll
        for (int ni = 0; ni < 8; ni++)
#pragma unroll
            for (int q = 0; q < 4; q++) acc[mi][ni][q] = 0.f;

    auto load_stage = [&](int st, int kp0) {
#pragma unroll
        for (int p = 0; p < 4; p++) {
            int cid = p * 128 + tid;
            int row = cid >> 2, c4 = cid & 3;
            int gr = bm + row;
            const uint32_t* srcp = A + (size_t)(gr < M ? gr : 0) * KP + kp0 + c4 * 4;
            uint32_t dst = (uint32_t)__cvta_generic_to_shared(&As[st][row][c4 * 4]);
            cp16(dst, srcp, (gr < M) ? 16 : 0);
        }
#pragma unroll
        for (int p = 0; p < 4; p++) {
            int cid = p * 128 + tid;
            int kr = cid >> 5, n4 = cid & 31;
            const uint32_t* srcp = Wh + (size_t)(kp0 + kr) * Nc + bn + n4 * 4;
            uint32_t dst = (uint32_t)__cvta_generic_to_shared(&Bs[st][kr][n4 * 4]);
            cp16(dst, srcp, 16);
        }
    };

    load_stage(0, 0);
    cp_commit();

    for (int kt = 0; kt < KT; kt++) {
        if (kt + 1 < KT) {
            load_stage((kt + 1) & 1, (kt + 1) << 4);
            cp_commit();
            cp_wait<1>();
        } else {
            cp_wait<0>();
        }
        __syncthreads();
        int st = kt & 1;
#pragma unroll
        for (int k8 = 0; k8 < 16; k8 += 8) {
            int kk = k8 + (lane & 3);
            uint32_t af[4][4];
#pragma unroll
            for (int mi = 0; mi < 4; mi++) {
                int mr = wm * 64 + mi * 16 + (lane >> 2);
                af[mi][0] = As[st][mr][kk];
                af[mi][1] = As[st][mr + 8][kk];
                af[mi][2] = As[st][mr][kk + 4];
                af[mi][3] = As[st][mr + 8][kk + 4];
            }
            uint32_t bf[8][2];
#pragma unroll
            for (int ni = 0; ni < 8; ni++) {
                int nc = wn * 64 + ni * 8 + (lane >> 2);
                bf[ni][0] = Bs[st][kk][nc];
                bf[ni][1] = Bs[st][kk + 4][nc];
            }
#pragma unroll
            for (int mi = 0; mi < 4; mi++)
#pragma unroll
                for (int ni = 0; ni < 8; ni++) mma_f16(acc[mi][ni], af[mi], bf[ni]);
        }
        __syncthreads();
    }
#pragma unroll
    for (int mi = 0; mi < 4; mi++) {
#pragma unroll
        for (int rr = 0; rr < 2; rr++) {
            int row = bm + wm * 64 + mi * 16 + (lane >> 2) + rr * 8;
            if (row >= M) continue;
#pragma unroll
            for (int ni = 0; ni < 8; ni++) {
                int col = bn + wn * 64 + ni * 8 + (lane & 3) * 2;
                float* p = C + (size_t)row * Nc + col;
                float2 v;
                v.x = acc[mi][ni][rr * 2 + 0] + bias[col] + p[0];
                v.y = acc[mi][ni][rr * 2 + 1] + bias[col + 1] + p[1];
                *(float2*)p = v;
            }
        }
    }
}

// ------------- pooling over sorted batch -------------------------------------
__global__ void pool_sum(const float* __restrict__ src, const int* __restrict__ batch,
                         float* __restrict__ out) {
    __shared__ int sb[512];
    int n0 = blockIdx.x * 512;
    int nend = min(n0 + 512, NN);
    for (int i = threadIdx.x; i < nend - n0; i += 256) sb[i] = batch[n0 + i];
    __syncthreads();
    int c = threadIdx.x;
    float acc = 0.f;
    int cur = sb[0];
    for (int n = n0; n < nend; n++) {
        int b = sb[n - n0];
        if (b != cur) {
            atomicAdd(&out[(size_t)cur * HH + c], acc);
            acc = 0.f;
            cur = b;
        }
        acc += src[(size_t)n * HH + c];
    }
    atomicAdd(&out[(size_t)cur * HH + c], acc);
}

// vn += vnsum*inv, then zero vnsum for next layer (saves a zero_f pass)
__global__ void vn_update(float* __restrict__ vn, float* __restrict__ vnsum,
                          const float* __restrict__ inv) {
    int i = blockIdx.x * blockDim.x + threadIdx.x;
    if (i < BBATCH * HH) {
        vn[i] += vnsum[i] * inv[i >> 8];
        vnsum[i] = 0.f;
    }
}

__global__ void scale_out(float* __restrict__ out, const float* __restrict__ inv) {
    int i = blockIdx.x * blockDim.x + threadIdx.x;
    if (i < BBATCH * HH) out[i] *= inv[i >> 8];
}

// ------------------------------ host orchestration ---------------------------
extern "C" void kernel_launch(void* const* d_in, const int* in_sizes, int n_in,
                              void* d_out, int out_size) {
    const float* x = (const float*)d_in[0];
    const int* eidx = (const int*)d_in[1];
    const float* eattr = (const float*)d_in[2];
    const int* batch = (const int*)d_in[3];
    const float* node_W = (const float*)d_in[4];
    const float* node_b = (const float*)d_in[5];
    const float* edge_W = (const float*)d_in[6];
    const float* edge_b = (const float*)d_in[7];
    const float* vn_emb = (const float*)d_in[8];
    const float* ln_g = (const float*)d_in[9];
    const float* ln_b = (const float*)d_in[10];
    const float* tt = (const float*)d_in[11];
    const float* W1 = (const float*)d_in[12];
    const float* b1 = (const float*)d_in[13];
    const float* mg = (const float*)d_in[14];
    const float* mb = (const float*)d_in[15];
    const float* W2 = (const float*)d_in[16];
    const float* b2 = (const float*)d_in[17];
    float* out = (float*)d_out;
    const int* srcp = eidx;
    const int* dstp = eidx + EE;

    float *h_, *hn_, *vn_, *vnsum_, *inv_;
    uint32_t *hnh_, *tmph_, *midh_, *w1h_, *w2h_;
    cudaGetSymbolAddress((void**)&h_, g_h);
    cudaGetSymbolAddress((void**)&hn_, g_hn);
    cudaGetSymbolAddress((void**)&hnh_, g_hnh);
    cudaGetSymbolAddress((void**)&tmph_, g_tmph);
    cudaGetSymbolAddress((void**)&midh_, g_midh);
    cudaGetSymbolAddress((void**)&vn_, g_vn);
    cudaGetSymbolAddress((void**)&vnsum_, g_vnsum);
    cudaGetSymbolAddress((void**)&inv_, g_inv);
    cudaGetSymbolAddress((void**)&w1h_, g_w1h);
    cudaGetSymbolAddress((void**)&w2h_, g_w2h);

    const int NB_SCAN = (NN + 1023) / 1024;
    const int NW = (HH / 2) * HB2;
    const int SMEM1 = 2 * (32 * 20 + 16 * 520) * 4;   // 71680
    const int SMEM2 = 2 * (128 * 20 + 16 * 136) * 4;  // 37888

    cudaFuncSetAttribute(gemm1_ln, cudaFuncAttributeMaxDynamicSharedMemorySize, SMEM1);
    cudaFuncSetAttribute(gemm2_pipe, cudaFuncAttributeMaxDynamicSharedMemorySize, SMEM2);

    // ---- setup ----
    zero_setup<<<(NN + 255) / 256, 256>>>();
    count_deg<<<(EE + 255) / 256, 256>>>(dstp);
    count_batch<<<(NN + 255) / 256, 256>>>(batch);
    scan_block<<<NB_SCAN, 1024>>>();
    scan_sums<<<1, 128>>>(NB_SCAN);
    add_offs<<<(NN + 255) / 256, 256>>>();
    csr_fill<<<(EE + 255) / 256, 256>>>(dstp);
    calc_inv<<<(BBATCH + 255) / 256, 256>>>();
    vn_init<<<(BBATCH * HH + 255) / 256, 256>>>(vn_, vn_emb);
    zero_f<<<(BBATCH * HH + 255) / 256, 256>>>(vnsum_, BBATCH * HH);
    for (int l = 0; l < 3; l++) {
        packWh<<<(NW + 255) / 256, 256>>>(W1 + (size_t)l * HH * HB2, w1h_ + (size_t)l * NW,
                                          HH, HB2);
        packWh<<<(NW + 255) / 256, 256>>>(W2 + (size_t)l * HB2 * HH, w2h_ + (size_t)l * NW,
                                          HB2, HH);
    }
    node_enc<<<NN, 256>>>(x, node_W, node_b, h_);

    // ---- layers 1..3 ----
    for (int l = 1; l < LLAYERS; l++) {
        if (l == 1)
            ln_relu256p<<<NN / 8, 256>>>(h_, hnh_, ln_g + l * HH, ln_b + l * HH);
        else
            vn_ln_relu_p<<<NN / 8, 256>>>(h_, hnh_, vn_, batch, ln_g + l * HH, ln_b + l * HH);
        aggregate<<<NN / 8, 256>>>(hnh_, srcp, eattr, edge_W, edge_b, tt + (l - 1), tmph_);
        gemm1_ln<<<(NN + 31) / 32, 256, SMEM1>>>(
            tmph_, w1h_ + (size_t)(l - 1) * NW, b1 + (l - 1) * HB2,
            mg + (l - 1) * HB2, mb + (l - 1) * HB2, midh_, NN);
        dim3 g2(HH / 128, (NN + 127) / 128);
        gemm2_pipe<<<g2, 128, SMEM2>>>(midh_, w2h_ + (size_t)(l - 1) * NW,
                                       b2 + (l - 1) * HH, h_, NN);
        pool_sum<<<(NN + 511) / 512, 256>>>(h_, batch, vnsum_);
        vn_update<<<(BBATCH * HH + 255) / 256, 256>>>(vn_, vnsum_, inv_);
    }

    // ---- final ----
    vn_ln_relu_f<<<NN / 8, 256>>>(h_, hn_, vn_, batch, ln_g, ln_b);
    zero_f<<<(BBATCH * HH + 255) / 256, 256>>>(out, BBATCH * HH);
    pool_sum<<<(NN + 511) / 512, 256>>>(hn_, batch, out);
    scale_out<<<(BBATCH * HH + 255) / 256, 256>>>(out, inv_);
}